// round 2
// baseline (speedup 1.0000x reference)
#include <cuda_runtime.h>

#define BB 16
#define NN 4096
#define DD 256
#define BN_TOT (BB*NN)          // 65536
#define EPSF 1e-6f
#define NCH 16                  // n-chunks for colsum & softmax partials

// ---- scratch (static device globals; no allocation anywhere) ----
__device__ float g_phiq[BN_TOT*DD];       // 64 MB
__device__ float g_phik[BN_TOT*DD];       // 64 MB
__device__ float g_rowsum[BN_TOT];
__device__ float g_colpart[BB*NCH*DD];
__device__ float g_colsum[BB*DD];
__device__ float g_pmax[BB*DD*NCH];
__device__ float g_psum[BB*DD*NCH];
__device__ float g_smax[BB*DD];
__device__ float g_sinv[BB*DD];
__device__ float g_kvpart[4*BB*DD*DD];    // 16 MB (split-K partials, deterministic)
__device__ float g_kv[BB*DD*DD];          // 4 MB

__device__ __forceinline__ float sigf(float x) { return 1.0f/(1.0f + __expf(-x)); }

// ============================================================
// K1: phi = sigmoid(X @ W + bias), X:[BN,D], W:[D,D], out selected by `which`
// 64x64 block tile, BK=16, 256 thr, 4x4 per thread
// ============================================================
__global__ __launch_bounds__(256) void k_phi(const float* __restrict__ X,
                                             const float* __restrict__ W,
                                             const float* __restrict__ bias,
                                             int which)
{
    __shared__ float Xs[16][64];
    __shared__ float Ws[16][64];
    float* out = which ? g_phik : g_phiq;
    const int tid = threadIdx.x;
    const int m0 = blockIdx.y * 64;
    const int e0 = blockIdx.x * 64;
    const int tx = tid & 15, ty = tid >> 4;
    const int lrow = tid >> 2, lkg = tid & 3;
    float acc[4][4] = {};
    for (int k0 = 0; k0 < DD; k0 += 16) {
        float4 xv = *reinterpret_cast<const float4*>(X + (m0 + lrow)*DD + k0 + lkg*4);
        Xs[lkg*4+0][lrow] = xv.x;
        Xs[lkg*4+1][lrow] = xv.y;
        Xs[lkg*4+2][lrow] = xv.z;
        Xs[lkg*4+3][lrow] = xv.w;
        *reinterpret_cast<float4*>(&Ws[ty][tx*4]) =
            *reinterpret_cast<const float4*>(W + (k0 + ty)*DD + e0 + tx*4);
        __syncthreads();
        #pragma unroll
        for (int kk = 0; kk < 16; kk++) {
            float4 a  = reinterpret_cast<float4*>(Xs[kk])[ty];
            float4 b4 = reinterpret_cast<float4*>(Ws[kk])[tx];
            float ar[4] = {a.x,a.y,a.z,a.w};
            float br[4] = {b4.x,b4.y,b4.z,b4.w};
            #pragma unroll
            for (int i=0;i<4;i++)
                #pragma unroll
                for (int j=0;j<4;j++)
                    acc[i][j] = fmaf(ar[i], br[j], acc[i][j]);
        }
        __syncthreads();
    }
    float4 bv = *reinterpret_cast<const float4*>(bias + e0 + tx*4);
    float bb[4] = {bv.x,bv.y,bv.z,bv.w};
    #pragma unroll
    for (int i=0;i<4;i++) {
        int row = m0 + ty*4 + i;
        float4 r;
        r.x = sigf(acc[i][0] + bb[0]);
        r.y = sigf(acc[i][1] + bb[1]);
        r.z = sigf(acc[i][2] + bb[2]);
        r.w = sigf(acc[i][3] + bb[3]);
        *reinterpret_cast<float4*>(out + row*DD + e0 + tx*4) = r;
    }
}

// ============================================================
// rowsum over D=256 of phi_q (one warp per row)
// ============================================================
__global__ __launch_bounds__(256) void k_rowsum()
{
    int row  = blockIdx.x*8 + (threadIdx.x >> 5);
    int lane = threadIdx.x & 31;
    const float* p = g_phiq + row*DD + lane*8;
    float4 v1 = *reinterpret_cast<const float4*>(p);
    float4 v2 = *reinterpret_cast<const float4*>(p+4);
    float s = v1.x+v1.y+v1.z+v1.w+v2.x+v2.y+v2.z+v2.w;
    #pragma unroll
    for (int o=16;o;o>>=1) s += __shfl_down_sync(0xffffffffu, s, o);
    if (lane==0) g_rowsum[row] = s;
}

// ============================================================
// colsum of phi_k over N (partials over n-chunks, then combine)
// ============================================================
__global__ __launch_bounds__(256) void k_colpart()
{
    int bc = blockIdx.x;                 // b*NCH + nc
    int b = bc / NCH, nc = bc % NCH;
    int d = threadIdx.x;
    const float* p = g_phik + (b*NN + nc*(NN/NCH))*DD + d;
    float s = 0.f;
    #pragma unroll 8
    for (int i=0;i<NN/NCH;i++) s += p[i*DD];
    g_colpart[bc*DD + d] = s;
}

__global__ __launch_bounds__(256) void k_colsum()
{
    int idx = blockIdx.x*256 + threadIdx.x;   // b*DD + d (4096 total)
    int b = idx >> 8, d = idx & 255;
    float s = 0.f;
    #pragma unroll
    for (int nc=0;nc<NCH;nc++) s += g_colpart[(b*NCH+nc)*DD + d];
    g_colsum[idx] = s;
}

// ============================================================
// softmax over n per (b,d) column of s = (phi_k*V)/(colsum+eps)
// pass 1: per-(n-chunk) online max/sum partials
// ============================================================
__global__ __launch_bounds__(128) void k_softpart(const float* __restrict__ V)
{
    int nc = blockIdx.x, dc = blockIdx.y, b = blockIdx.z;
    int tid = threadIdx.x;
    int dl = tid & 31, ng = tid >> 5;    // 32 cols x 4 n-groups
    int d = dc*32 + dl;
    float c = 1.0f/(g_colsum[b*DD + d] + EPSF);
    float m = -3.4e38f, s = 0.f;
    int n0 = nc*(NN/NCH);
    const float* pk = g_phik + (b*NN + n0)*DD + d;
    const float* pv = V      + (b*NN + n0)*DD + d;
    for (int i = ng; i < NN/NCH; i += 4) {
        float v = (pk[i*DD]*pv[i*DD])*c;
        float nm = fmaxf(m, v);
        s = s*__expf(m-nm) + __expf(v-nm);
        m = nm;
    }
    __shared__ float shm[128], shs[128];
    shm[tid]=m; shs[tid]=s; __syncthreads();
    if (tid < 64) {
        float m2=shm[tid+64], s2=shs[tid+64];
        float M=fmaxf(shm[tid],m2);
        shs[tid] = shs[tid]*__expf(shm[tid]-M) + s2*__expf(m2-M);
        shm[tid] = M;
    }
    __syncthreads();
    if (tid < 32) {
        float m2=shm[tid+32], s2=shs[tid+32];
        float M=fmaxf(shm[tid],m2);
        float S = shs[tid]*__expf(shm[tid]-M) + s2*__expf(m2-M);
        g_pmax[(b*DD+d)*NCH + nc] = M;
        g_psum[(b*DD+d)*NCH + nc] = S;
    }
}

__global__ __launch_bounds__(256) void k_softcombine()
{
    int idx = blockIdx.x*256 + threadIdx.x;   // 4096 columns
    float M = -3.4e38f;
    #pragma unroll
    for (int nc=0;nc<NCH;nc++) M = fmaxf(M, g_pmax[idx*NCH+nc]);
    float Z = 0.f;
    #pragma unroll
    for (int nc=0;nc<NCH;nc++) Z += g_psum[idx*NCH+nc]*__expf(g_pmax[idx*NCH+nc]-M);
    g_smax[idx] = M;
    g_sinv[idx] = 1.0f/Z;
}

// pass 2: V_b = exp(s - M) * invZ  (written into d_out as scratch)
__global__ __launch_bounds__(256) void k_writevb(const float* __restrict__ V, float* __restrict__ vb)
{
    int i4 = blockIdx.x*256 + threadIdx.x;    // over BN*D/4
    int base = i4*4;
    int d0 = base & 255;
    int bn = base >> 8;
    int b  = bn >> 12;
    int cb = b*DD + d0;
    float4 pk = *reinterpret_cast<const float4*>(&g_phik[base]);
    float4 vv = *reinterpret_cast<const float4*>(&V[base]);
    float pks[4]={pk.x,pk.y,pk.z,pk.w};
    float vvs[4]={vv.x,vv.y,vv.z,vv.w};
    float o[4];
    #pragma unroll
    for (int j=0;j<4;j++) {
        float c = 1.0f/(g_colsum[cb+j] + EPSF);
        float s = (pks[j]*vvs[j])*c;
        o[j] = __expf(s - g_smax[cb+j]) * g_sinv[cb+j];
    }
    float4 r = {o[0],o[1],o[2],o[3]};
    *reinterpret_cast<float4*>(&vb[base]) = r;
}

// ============================================================
// KV[b] = phi_k[b]^T @ V_b[b]  (K=4096, split-K x4, deterministic)
// ============================================================
__global__ __launch_bounds__(256) void k_kv(const float* __restrict__ vb)
{
    __shared__ float As[16][64];    // [n(k)][d]
    __shared__ float Bs[16][64];    // [n(k)][e]
    int tid = threadIdx.x;
    int e0 = blockIdx.x*64, d0 = blockIdx.y*64;
    int b = blockIdx.z >> 2, ks = blockIdx.z & 3;
    const float* A  = g_phik + b*NN*DD;
    const float* Bv = vb     + b*NN*DD;
    int tx = tid & 15, ty = tid >> 4;
    float acc[4][4] = {};
    int kbeg = ks*(NN/4), kend = kbeg + NN/4;
    for (int k0 = kbeg; k0 < kend; k0 += 16) {
        *reinterpret_cast<float4*>(&As[ty][tx*4]) =
            *reinterpret_cast<const float4*>(A + (k0+ty)*DD + d0 + tx*4);
        *reinterpret_cast<float4*>(&Bs[ty][tx*4]) =
            *reinterpret_cast<const float4*>(Bv + (k0+ty)*DD + e0 + tx*4);
        __syncthreads();
        #pragma unroll
        for (int kk=0;kk<16;kk++) {
            float4 a  = reinterpret_cast<float4*>(As[kk])[ty];
            float4 b4 = reinterpret_cast<float4*>(Bs[kk])[tx];
            float ar[4] = {a.x,a.y,a.z,a.w};
            float br[4] = {b4.x,b4.y,b4.z,b4.w};
            #pragma unroll
            for (int i=0;i<4;i++)
                #pragma unroll
                for (int j=0;j<4;j++)
                    acc[i][j] = fmaf(ar[i], br[j], acc[i][j]);
        }
        __syncthreads();
    }
    float* outp = g_kvpart + ks*(BB*DD*DD) + b*DD*DD;
    #pragma unroll
    for (int i=0;i<4;i++) {
        int row = d0 + ty*4 + i;
        float4 r = {acc[i][0],acc[i][1],acc[i][2],acc[i][3]};
        *reinterpret_cast<float4*>(outp + row*DD + e0 + tx*4) = r;
    }
}

__global__ __launch_bounds__(256) void k_kvsum()
{
    int idx = blockIdx.x*256 + threadIdx.x;   // BB*DD*DD
    const int S = BB*DD*DD;
    g_kv[idx] = ((g_kvpart[idx] + g_kvpart[idx+S]) + (g_kvpart[idx+2*S] + g_kvpart[idx+3*S]));
}

// ============================================================
// R = [sigmoid(rs)/(rs+eps)] * (phi_q @ KV[b])
// ============================================================
__global__ __launch_bounds__(256) void k_out(float* __restrict__ out)
{
    __shared__ float Xs[16][64];
    __shared__ float Ws[16][64];
    const int tid = threadIdx.x;
    const int m0 = blockIdx.y * 64;
    const int e0 = blockIdx.x * 64;
    const int b  = m0 >> 12;                 // /NN
    const float* X = g_phiq;
    const float* W = g_kv + b*DD*DD;
    const int tx = tid & 15, ty = tid >> 4;
    const int lrow = tid >> 2, lkg = tid & 3;
    float acc[4][4] = {};
    for (int k0 = 0; k0 < DD; k0 += 16) {
        float4 xv = *reinterpret_cast<const float4*>(X + (m0 + lrow)*DD + k0 + lkg*4);
        Xs[lkg*4+0][lrow] = xv.x;
        Xs[lkg*4+1][lrow] = xv.y;
        Xs[lkg*4+2][lrow] = xv.z;
        Xs[lkg*4+3][lrow] = xv.w;
        *reinterpret_cast<float4*>(&Ws[ty][tx*4]) =
            *reinterpret_cast<const float4*>(W + (k0 + ty)*DD + e0 + tx*4);
        __syncthreads();
        #pragma unroll
        for (int kk = 0; kk < 16; kk++) {
            float4 a  = reinterpret_cast<float4*>(Xs[kk])[ty];
            float4 b4 = reinterpret_cast<float4*>(Ws[kk])[tx];
            float ar[4] = {a.x,a.y,a.z,a.w};
            float br[4] = {b4.x,b4.y,b4.z,b4.w};
            #pragma unroll
            for (int i=0;i<4;i++)
                #pragma unroll
                for (int j=0;j<4;j++)
                    acc[i][j] = fmaf(ar[i], br[j], acc[i][j]);
        }
        __syncthreads();
    }
    #pragma unroll
    for (int i=0;i<4;i++) {
        int row = m0 + ty*4 + i;
        float rs = g_rowsum[row];
        float scale = sigf(rs) / (rs + EPSF);
        float4 r;
        r.x = acc[i][0]*scale;
        r.y = acc[i][1]*scale;
        r.z = acc[i][2]*scale;
        r.w = acc[i][3]*scale;
        *reinterpret_cast<float4*>(out + row*DD + e0 + tx*4) = r;
    }
}

// ============================================================
extern "C" void kernel_launch(void* const* d_in, const int* in_sizes, int n_in,
                              void* d_out, int out_size)
{
    const float* Q  = (const float*)d_in[0];
    const float* K  = (const float*)d_in[1];
    const float* V  = (const float*)d_in[2];
    const float* Wq = (const float*)d_in[3];
    const float* bq = (const float*)d_in[4];
    const float* Wk = (const float*)d_in[5];
    const float* bk = (const float*)d_in[6];
    float* out = (float*)d_out;
    (void)in_sizes; (void)n_in; (void)out_size;

    dim3 gphi(4, 1024);
    k_phi<<<gphi, 256>>>(Q, Wq, bq, 0);               // phi_q
    k_phi<<<gphi, 256>>>(K, Wk, bk, 1);               // phi_k
    k_rowsum<<<BN_TOT/8, 256>>>();                    // sum_d phi_q
    k_colpart<<<BB*NCH, 256>>>();                     // partial sum_n phi_k
    k_colsum<<<16, 256>>>();
    k_softpart<<<dim3(NCH, 8, BB), 128>>>(V);         // column softmax partials
    k_softcombine<<<16, 256>>>();
    k_writevb<<<(BN_TOT*DD/4)/256, 256>>>(V, out);    // V_b -> d_out (scratch)
    k_kv<<<dim3(4,4,BB*4), 256>>>(out);               // split-K KV partials
    k_kvsum<<<BB*DD*DD/256, 256>>>();
    k_out<<<gphi, 256>>>(out);                        // final R
}

// round 5
// speedup vs baseline: 2.3447x; 2.3447x over previous
#include <cuda_runtime.h>
#include <cstdint>

#define BB 16
#define NN 4096
#define DD 256
#define BN_TOT (BB*NN)          // 65536
#define EPSF 1e-6f
#define NCH 16

// ---------------- scratch ----------------
__device__ float g_phiq[BN_TOT*DD];       // [bn][d] 64MB
__device__ float g_phik[BN_TOT*DD];       // [bn][d] 64MB
__device__ float g_rowsum[BN_TOT];
__device__ float g_colpart[BB*NCH*DD];
__device__ float g_colsum[BB*DD];
__device__ float g_pmax[BB*DD*NCH];
__device__ float g_psum[BB*DD*NCH];
__device__ float g_smax[BB*DD];
__device__ float g_sinv[BB*DD];
__device__ float g_kvpart[4*BB*DD*DD];
__device__ float g_kv[BB*DD*DD];

__device__ __forceinline__ float sigf(float x){ return 1.0f/(1.0f + __expf(-x)); }
__device__ __forceinline__ float t32(float a){
    uint32_t u; asm("cvt.rna.tf32.f32 %0, %1;" : "=r"(u) : "f"(a)); return __uint_as_float(u);
}
__device__ __forceinline__ void mma8(float* d, const uint32_t* a, const uint32_t* b){
    asm volatile("mma.sync.aligned.m16n8k8.row.col.f32.tf32.tf32.f32 "
        "{%0,%1,%2,%3}, {%4,%5,%6,%7}, {%8,%9}, {%0,%1,%2,%3};"
        : "+f"(d[0]), "+f"(d[1]), "+f"(d[2]), "+f"(d[3])
        : "r"(a[0]), "r"(a[1]), "r"(a[2]), "r"(a[3]), "r"(b[0]), "r"(b[1]));
}

// ---------------- tf32 warp-mma GEMM core ----------------
// CTA tile: 128(M) x 128(N), BK=32, 256 threads, warps 4(M) x 2(N), warp tile 32x64.
// AMODE 0: A memory is [m][k], lda over m. AMODE 1: A memory is [k][m], lda over k
// (i.e. the logical A is the transpose of what's in memory — frag indexing transposes).
// B memory is [k][n], ldb over k. acc[mf][nf][4] per thread.
#define PA0 36
#define PA1 136
#define PB  136

template<int AMODE>
__device__ __forceinline__ void gemm_core(const float* __restrict__ A, int lda,
                                          const float* __restrict__ B, int ldb,
                                          int kchunks, float acc[2][8][4],
                                          float* As, float* Bs){
    const int tid = threadIdx.x;
    const int wid = tid >> 5, lane = tid & 31;
    const int wm = wid & 3, wn = wid >> 2;
    const int g = lane >> 2, c4 = lane & 3;

    #pragma unroll
    for (int mf = 0; mf < 2; mf++)
        #pragma unroll
        for (int nf = 0; nf < 8; nf++)
            #pragma unroll
            for (int j = 0; j < 4; j++) acc[mf][nf][j] = 0.f;

    for (int ch = 0; ch < kchunks; ch++){
        // --- stage A ---
        if (AMODE == 0){
            #pragma unroll
            for (int i = 0; i < 4; i++){
                int idx = tid + i*256;              // 1024 float4s: 128m x 8kq
                int m = idx >> 3, kq = idx & 7;
                float4 v = *reinterpret_cast<const float4*>(A + (size_t)m*lda + ch*32 + kq*4);
                v.x=t32(v.x); v.y=t32(v.y); v.z=t32(v.z); v.w=t32(v.w);
                *reinterpret_cast<float4*>(As + m*PA0 + kq*4) = v;
            }
        } else {
            #pragma unroll
            for (int i = 0; i < 4; i++){
                int idx = tid + i*256;              // 32k x 32mq
                int kr = idx >> 5, mq = idx & 31;
                float4 v = *reinterpret_cast<const float4*>(A + (size_t)(ch*32 + kr)*lda + mq*4);
                v.x=t32(v.x); v.y=t32(v.y); v.z=t32(v.z); v.w=t32(v.w);
                *reinterpret_cast<float4*>(As + kr*PA1 + mq*4) = v;
            }
        }
        // --- stage B ---
        #pragma unroll
        for (int i = 0; i < 4; i++){
            int idx = tid + i*256;                  // 32k x 32nq
            int kr = idx >> 5, nq = idx & 31;
            float4 v = *reinterpret_cast<const float4*>(B + (size_t)(ch*32 + kr)*ldb + nq*4);
            v.x=t32(v.x); v.y=t32(v.y); v.z=t32(v.z); v.w=t32(v.w);
            *reinterpret_cast<float4*>(Bs + kr*PB + nq*4) = v;
        }
        __syncthreads();

        #pragma unroll
        for (int ks = 0; ks < 4; ks++){
            const int kb = ks*8;
            uint32_t a[2][4], bf[8][2];
            #pragma unroll
            for (int mf = 0; mf < 2; mf++){
                int row = wm*32 + mf*16 + g;
                if (AMODE == 0){
                    a[mf][0] = __float_as_uint(As[(row  )*PA0 + kb + c4    ]);
                    a[mf][1] = __float_as_uint(As[(row+8)*PA0 + kb + c4    ]);
                    a[mf][2] = __float_as_uint(As[(row  )*PA0 + kb + c4 + 4]);
                    a[mf][3] = __float_as_uint(As[(row+8)*PA0 + kb + c4 + 4]);
                } else {
                    a[mf][0] = __float_as_uint(As[(kb+c4  )*PA1 + row    ]);
                    a[mf][1] = __float_as_uint(As[(kb+c4  )*PA1 + row + 8]);
                    a[mf][2] = __float_as_uint(As[(kb+c4+4)*PA1 + row    ]);
                    a[mf][3] = __float_as_uint(As[(kb+c4+4)*PA1 + row + 8]);
                }
            }
            #pragma unroll
            for (int nf = 0; nf < 8; nf++){
                int ncol = wn*64 + nf*8 + g;
                bf[nf][0] = __float_as_uint(Bs[(kb+c4  )*PB + ncol]);
                bf[nf][1] = __float_as_uint(Bs[(kb+c4+4)*PB + ncol]);
            }
            #pragma unroll
            for (int mf = 0; mf < 2; mf++)
                #pragma unroll
                for (int nf = 0; nf < 8; nf++)
                    mma8(acc[mf][nf], a[mf], bf[nf]);
        }
        __syncthreads();
    }
}

// ================= GEMM kernels =================
// phi = sigmoid(X @ W + b); grid (2, 512): x -> e-tile, y -> m-tile
__global__ __launch_bounds__(256, 2) void k_phi(const float* __restrict__ X,
                                                const float* __restrict__ W,
                                                const float* __restrict__ bias, int which){
    __shared__ float As[128*PA0];
    __shared__ float Bs[32*PB];
    float* out = which ? g_phik : g_phiq;
    const int m0 = blockIdx.y * 128, e0 = blockIdx.x * 128;
    float acc[2][8][4];
    gemm_core<0>(X + (size_t)m0*DD, DD, W + e0, DD, 8, acc, As, Bs);

    const int wid = threadIdx.x >> 5, lane = threadIdx.x & 31;
    const int wm = wid & 3, wn = wid >> 2, g = lane >> 2, c4 = lane & 3;
    #pragma unroll
    for (int mf = 0; mf < 2; mf++){
        int row = m0 + wm*32 + mf*16 + g;
        #pragma unroll
        for (int nf = 0; nf < 8; nf++){
            int col = e0 + wn*64 + nf*8 + c4*2;
            float b0 = bias[col], b1 = bias[col+1];
            float2 r0 = { sigf(acc[mf][nf][0] + b0), sigf(acc[mf][nf][1] + b1) };
            float2 r1 = { sigf(acc[mf][nf][2] + b0), sigf(acc[mf][nf][3] + b1) };
            *reinterpret_cast<float2*>(out + (size_t)row*DD + col)     = r0;
            *reinterpret_cast<float2*>(out + (size_t)(row+8)*DD + col) = r1;
        }
    }
}

// KV partials: KV[b] = phi_k[b]^T @ V_b[b]; split-K x4. grid (2, 2, BB*4)
__global__ __launch_bounds__(256, 2) void k_kv(const float* __restrict__ vb){
    __shared__ float As[32*PA1];
    __shared__ float Bs[32*PB];
    const int e0 = blockIdx.x * 128, d0 = blockIdx.y * 128;
    const int b = blockIdx.z >> 2, ks = blockIdx.z & 3;
    const float* A  = g_phik + (size_t)(b*NN + ks*1024)*DD + d0;   // [k=n][m=d]
    const float* Bv = vb     + (size_t)(b*NN + ks*1024)*DD + e0;   // [k=n][n=e]
    float acc[2][8][4];
    gemm_core<1>(A, DD, Bv, DD, 32, acc, As, Bs);

    const int wid = threadIdx.x >> 5, lane = threadIdx.x & 31;
    const int wm = wid & 3, wn = wid >> 2, g = lane >> 2, c4 = lane & 3;
    float* part = g_kvpart + (size_t)(ks*BB + b)*DD*DD;
    #pragma unroll
    for (int mf = 0; mf < 2; mf++){
        int row = d0 + wm*32 + mf*16 + g;
        #pragma unroll
        for (int nf = 0; nf < 8; nf++){
            int col = e0 + wn*64 + nf*8 + c4*2;
            float2 r0 = { acc[mf][nf][0], acc[mf][nf][1] };
            float2 r1 = { acc[mf][nf][2], acc[mf][nf][3] };
            *reinterpret_cast<float2*>(part + (size_t)row*DD + col)     = r0;
            *reinterpret_cast<float2*>(part + (size_t)(row+8)*DD + col) = r1;
        }
    }
}

// R = gate(rowsum) * (phi_q @ KV[b]); grid (2, 512)
__global__ __launch_bounds__(256, 2) void k_out(float* __restrict__ out){
    __shared__ float As[128*PA0];
    __shared__ float Bs[32*PB];
    const int m0 = blockIdx.y * 128, e0 = blockIdx.x * 128;
    const int b = m0 >> 12;
    float acc[2][8][4];
    gemm_core<0>(g_phiq + (size_t)m0*DD, DD, g_kv + (size_t)b*DD*DD + e0, DD, 8, acc, As, Bs);

    const int wid = threadIdx.x >> 5, lane = threadIdx.x & 31;
    const int wm = wid & 3, wn = wid >> 2, g = lane >> 2, c4 = lane & 3;
    #pragma unroll
    for (int mf = 0; mf < 2; mf++){
        int row = m0 + wm*32 + mf*16 + g;
        float rs0 = g_rowsum[row],   sc0 = sigf(rs0) / (rs0 + EPSF);
        float rs1 = g_rowsum[row+8], sc1 = sigf(rs1) / (rs1 + EPSF);
        #pragma unroll
        for (int nf = 0; nf < 8; nf++){
            int col = e0 + wn*64 + nf*8 + c4*2;
            float2 r0 = { acc[mf][nf][0]*sc0, acc[mf][nf][1]*sc0 };
            float2 r1 = { acc[mf][nf][2]*sc1, acc[mf][nf][3]*sc1 };
            *reinterpret_cast<float2*>(out + (size_t)row*DD + col)     = r0;
            *reinterpret_cast<float2*>(out + (size_t)(row+8)*DD + col) = r1;
        }
    }
}

// ================= elementwise kernels (round-1, known-correct) =================
__global__ __launch_bounds__(256) void k_rowsum(){
    int row  = blockIdx.x*8 + (threadIdx.x >> 5);
    int lane = threadIdx.x & 31;
    const float* p = g_phiq + (size_t)row*DD + lane*8;
    float4 v1 = *reinterpret_cast<const float4*>(p);
    float4 v2 = *reinterpret_cast<const float4*>(p+4);
    float s = v1.x+v1.y+v1.z+v1.w+v2.x+v2.y+v2.z+v2.w;
    #pragma unroll
    for (int o=16;o;o>>=1) s += __shfl_down_sync(0xffffffffu, s, o);
    if (lane==0) g_rowsum[row] = s;
}

__global__ __launch_bounds__(256) void k_colpart(){
    int bc = blockIdx.x;
    int b = bc / NCH, nc = bc % NCH;
    int d = threadIdx.x;
    const float* p = g_phik + (size_t)(b*NN + nc*(NN/NCH))*DD + d;
    float s = 0.f;
    #pragma unroll 8
    for (int i=0;i<NN/NCH;i++) s += p[(size_t)i*DD];
    g_colpart[bc*DD + d] = s;
}

__global__ __launch_bounds__(256) void k_colsum(){
    int idx = blockIdx.x*256 + threadIdx.x;
    int b = idx >> 8, d = idx & 255;
    float s = 0.f;
    #pragma unroll
    for (int nc=0;nc<NCH;nc++) s += g_colpart[(b*NCH+nc)*DD + d];
    g_colsum[idx] = s;
}

__global__ __launch_bounds__(128) void k_softpart(const float* __restrict__ V){
    int nc = blockIdx.x, dc = blockIdx.y, b = blockIdx.z;
    int tid = threadIdx.x;
    int dl = tid & 31, ng = tid >> 5;
    int d = dc*32 + dl;
    float c = 1.0f/(g_colsum[b*DD + d] + EPSF);
    float m = -3.4e38f, s = 0.f;
    int n0 = nc*(NN/NCH);
    const float* pk = g_phik + (size_t)(b*NN + n0)*DD + d;
    const float* pv = V      + (size_t)(b*NN + n0)*DD + d;
    for (int i = ng; i < NN/NCH; i += 4) {
        float v = (pk[(size_t)i*DD]*pv[(size_t)i*DD])*c;
        float nm = fmaxf(m, v);
        s = s*__expf(m-nm) + __expf(v-nm);
        m = nm;
    }
    __shared__ float shm[128], shs[128];
    shm[tid]=m; shs[tid]=s; __syncthreads();
    if (tid < 64) {
        float m2=shm[tid+64], s2=shs[tid+64];
        float M=fmaxf(shm[tid],m2);
        shs[tid] = shs[tid]*__expf(shm[tid]-M) + s2*__expf(m2-M);
        shm[tid] = M;
    }
    __syncthreads();
    if (tid < 32) {
        float m2=shm[tid+32], s2=shs[tid+32];
        float M=fmaxf(shm[tid],m2);
        float S = shs[tid]*__expf(shm[tid]-M) + s2*__expf(m2-M);
        g_pmax[(b*DD+d)*NCH + nc] = M;
        g_psum[(b*DD+d)*NCH + nc] = S;
    }
}

__global__ __launch_bounds__(256) void k_softcombine(){
    int idx = blockIdx.x*256 + threadIdx.x;
    float M = -3.4e38f;
    #pragma unroll
    for (int nc=0;nc<NCH;nc++) M = fmaxf(M, g_pmax[idx*NCH+nc]);
    float Z = 0.f;
    #pragma unroll
    for (int nc=0;nc<NCH;nc++) Z += g_psum[idx*NCH+nc]*__expf(g_pmax[idx*NCH+nc]-M);
    g_smax[idx] = M;
    g_sinv[idx] = 1.0f/Z;
}

__global__ __launch_bounds__(256) void k_writevb(const float* __restrict__ V, float* __restrict__ vb){
    int i4 = blockIdx.x*256 + threadIdx.x;
    size_t base = (size_t)i4*4;
    int d0 = (int)(base & 255);
    int bn = (int)(base >> 8);
    int b  = bn >> 12;
    int cb = b*DD + d0;
    float4 pk = *reinterpret_cast<const float4*>(&g_phik[base]);
    float4 vv = *reinterpret_cast<const float4*>(&V[base]);
    float pks[4]={pk.x,pk.y,pk.z,pk.w};
    float vvs[4]={vv.x,vv.y,vv.z,vv.w};
    float o[4];
    #pragma unroll
    for (int j=0;j<4;j++) {
        float c = 1.0f/(g_colsum[cb+j] + EPSF);
        float s = (pks[j]*vvs[j])*c;
        o[j] = __expf(s - g_smax[cb+j]) * g_sinv[cb+j];
    }
    float4 r = {o[0],o[1],o[2],o[3]};
    *reinterpret_cast<float4*>(&vb[base]) = r;
}

__global__ __launch_bounds__(256) void k_kvsum(){
    int idx = blockIdx.x*256 + threadIdx.x;
    const int S = BB*DD*DD;
    g_kv[idx] = ((g_kvpart[idx] + g_kvpart[idx+S]) + (g_kvpart[idx+2*S] + g_kvpart[idx+3*S]));
}

// ================= launch =================
extern "C" void kernel_launch(void* const* d_in, const int* in_sizes, int n_in,
                              void* d_out, int out_size){
    const float* Q  = (const float*)d_in[0];
    const float* K  = (const float*)d_in[1];
    const float* V  = (const float*)d_in[2];
    const float* Wq = (const float*)d_in[3];
    const float* bq = (const float*)d_in[4];
    const float* Wk = (const float*)d_in[5];
    const float* bk = (const float*)d_in[6];
    float* out = (float*)d_out;
    (void)in_sizes; (void)n_in; (void)out_size;

    k_phi<<<dim3(2,512), 256>>>(Q, Wq, bq, 0);      // phi_q [bn][d]
    k_phi<<<dim3(2,512), 256>>>(K, Wk, bk, 1);      // phi_k [bn][d]
    k_rowsum<<<BN_TOT/8, 256>>>();
    k_colpart<<<BB*NCH, 256>>>();
    k_colsum<<<16, 256>>>();
    k_softpart<<<dim3(NCH, 8, BB), 128>>>(V);
    k_softcombine<<<16, 256>>>();
    k_writevb<<<(BN_TOT*DD/4)/256, 256>>>(V, out);  // V_b -> d_out scratch
    k_kv<<<dim3(2,2,BB*4), 256>>>(out);             // split-K KV partials
    k_kvsum<<<BB*DD*DD/256, 256>>>();
    k_out<<<dim3(2,512), 256>>>(out);               // final R
}